// round 2
// baseline (speedup 1.0000x reference)
#include <cuda_runtime.h>
#include <cuda_bf16.h>
#include <cstdint>

// Problem constants
#define B_   4
#define T_   2048
#define DIM_ 1024
#define H_   16
#define HD_  64
#define NTOK (B_ * T_)          // 8192
#define QKV_COLS (3 * DIM_)     // 3072

// Scratch in device globals (no allocations allowed)
__device__ float g_qkv[(size_t)NTOK * QKV_COLS];   // ~100.7 MB
__device__ float g_attn[(size_t)NTOK * DIM_];      // ~33.5 MB

// ---------------------------------------------------------------------------
// SGEMM: C[M,N] = A[M,K] @ B[K,N], all row-major, dims divisible by tiles.
// 128x128 block tile, BK=16, 256 threads, 8x8 per-thread microtile.
// ---------------------------------------------------------------------------
#define BM 128
#define BN 128
#define BK 16
#define TM 8
#define TN 8

__global__ __launch_bounds__(256) void sgemm_kernel(
    int M, int N, int K,
    const float* __restrict__ A, const float* __restrict__ Bm,
    float* __restrict__ C)
{
    __shared__ float As[BK][BM];
    __shared__ float Bs[BK][BN];

    const int tid = threadIdx.x;
    const int tcol = tid % (BN / TN);   // 0..15
    const int trow = tid / (BN / TN);   // 0..15

    const float* Ablk = A + (size_t)blockIdx.y * BM * K;
    const float* Bblk = Bm + (size_t)blockIdx.x * BN;

    // A tile load mapping: 128 rows x 16 cols -> 512 float4, 2 per thread
    const int a_row  = tid / (BK / 4);          // 0..63
    const int a_col4 = (tid % (BK / 4)) * 4;    // 0,4,8,12
    // B tile load mapping: 16 rows x 128 cols -> 512 float4, 2 per thread
    const int b_row  = tid / (BN / 4);          // 0..7
    const int b_col4 = (tid % (BN / 4)) * 4;

    float acc[TM][TN] = {};
    float regA[TM], regB[TN];

    for (int k0 = 0; k0 < K; k0 += BK) {
        #pragma unroll
        for (int i = 0; i < 2; i++) {
            int r = a_row + i * 64;
            float4 v = *reinterpret_cast<const float4*>(Ablk + (size_t)r * K + k0 + a_col4);
            As[a_col4 + 0][r] = v.x;
            As[a_col4 + 1][r] = v.y;
            As[a_col4 + 2][r] = v.z;
            As[a_col4 + 3][r] = v.w;
        }
        #pragma unroll
        for (int i = 0; i < 2; i++) {
            int r = b_row + i * 8;
            float4 v = *reinterpret_cast<const float4*>(Bblk + (size_t)(k0 + r) * N + b_col4);
            *reinterpret_cast<float4*>(&Bs[r][b_col4]) = v;
        }
        __syncthreads();

        #pragma unroll
        for (int kk = 0; kk < BK; kk++) {
            #pragma unroll
            for (int i = 0; i < TM; i++) regA[i] = As[kk][trow * TM + i];
            #pragma unroll
            for (int j = 0; j < TN; j++) regB[j] = Bs[kk][tcol * TN + j];
            #pragma unroll
            for (int i = 0; i < TM; i++)
                #pragma unroll
                for (int j = 0; j < TN; j++)
                    acc[i][j] += regA[i] * regB[j];
        }
        __syncthreads();
    }

    float* Cblk = C + (size_t)blockIdx.y * BM * N + (size_t)blockIdx.x * BN;
    #pragma unroll
    for (int i = 0; i < TM; i++) {
        #pragma unroll
        for (int j = 0; j < TN; j += 4) {
            float4 v = make_float4(acc[i][j], acc[i][j + 1], acc[i][j + 2], acc[i][j + 3]);
            *reinterpret_cast<float4*>(Cblk + (size_t)(trow * TM + i) * N + tcol * TN + j) = v;
        }
    }
}

// ---------------------------------------------------------------------------
// Flash-attention style kernel with fused RoPE: one block = (128 queries,
// one (b,h)). One thread per query: q (RoPE-rotated + scaled) and output acc
// in registers; K tiles RoPE-rotated while staging into smem; V tiles plain.
// Inner reads are warp-uniform -> smem broadcast. Online softmax, 16-wide
// score chunks to bound register count.
// ---------------------------------------------------------------------------
#define BQ 128
#define BKV 64

__global__ __launch_bounds__(128) void attn_kernel(
    const float* __restrict__ qkv,
    const float* __restrict__ cosT,   // [T, HD/2]
    const float* __restrict__ sinT,   // [T, HD/2]
    float* __restrict__ out)
{
    const int bh = blockIdx.y;          // 0..63
    const int b  = bh / H_;
    const int h  = bh % H_;
    const int qt = blockIdx.x * BQ + threadIdx.x;   // query position in T

    const float scale = 0.125f;         // HD^-0.5

    // Load q row and apply RoPE + scale in registers.
    const float* qrow = qkv + ((size_t)(b * T_ + qt) * QKV_COLS) + h * HD_;
    float q[HD_];
    #pragma unroll
    for (int i = 0; i < HD_ / 2; i++) {
        float c = cosT[qt * (HD_ / 2) + i];
        float s = sinT[qt * (HD_ / 2) + i];
        float e = qrow[2 * i], o = qrow[2 * i + 1];
        q[2 * i]     = (e * c - o * s) * scale;
        q[2 * i + 1] = (e * s + o * c) * scale;
    }

    float acc[HD_] = {};
    float m = -1e30f, l = 0.f;

    __shared__ float Ks[BKV][HD_];
    __shared__ float Vs[BKV][HD_];

    for (int k0 = 0; k0 < T_; k0 += BKV) {
        __syncthreads();
        // Load K,V tile: 64x64 floats each = 8 float4 per thread per tensor.
        // K gets RoPE applied during staging (pairs are adjacent lanes of the
        // float4, so rotation is local to the vector).
        #pragma unroll
        for (int i = 0; i < (BKV * HD_) / (128 * 4); i++) {
            int off = (i * 128 + threadIdx.x) * 4;
            int r = off / HD_, c = off % HD_;
            int kt = k0 + r;
            const float* base = qkv + (size_t)(b * T_ + kt) * QKV_COLS + h * HD_ + c;
            float4 kv = *reinterpret_cast<const float4*>(base + DIM_);
            float c0 = cosT[kt * (HD_ / 2) + c / 2];
            float s0 = sinT[kt * (HD_ / 2) + c / 2];
            float c1 = cosT[kt * (HD_ / 2) + c / 2 + 1];
            float s1 = sinT[kt * (HD_ / 2) + c / 2 + 1];
            float4 kr;
            kr.x = kv.x * c0 - kv.y * s0;
            kr.y = kv.x * s0 + kv.y * c0;
            kr.z = kv.z * c1 - kv.w * s1;
            kr.w = kv.z * s1 + kv.w * c1;
            *reinterpret_cast<float4*>(&Ks[r][c]) = kr;
            *reinterpret_cast<float4*>(&Vs[r][c]) =
                *reinterpret_cast<const float4*>(base + 2 * DIM_);
        }
        __syncthreads();

        #pragma unroll 1
        for (int j0 = 0; j0 < BKV; j0 += 16) {
            float sc[16];
            float mt = m;
            #pragma unroll
            for (int jj = 0; jj < 16; jj++) {
                float s = 0.f;
                #pragma unroll
                for (int d = 0; d < HD_; d += 4) {
                    float4 kv = *reinterpret_cast<const float4*>(&Ks[j0 + jj][d]);
                    s += q[d] * kv.x + q[d + 1] * kv.y + q[d + 2] * kv.z + q[d + 3] * kv.w;
                }
                sc[jj] = s;
                mt = fmaxf(mt, s);
            }
            float corr = __expf(m - mt);
            l *= corr;
            #pragma unroll
            for (int d = 0; d < HD_; d++) acc[d] *= corr;
            m = mt;
            #pragma unroll
            for (int jj = 0; jj < 16; jj++) {
                float p = __expf(sc[jj] - mt);
                l += p;
                #pragma unroll
                for (int d = 0; d < HD_; d += 4) {
                    float4 vv = *reinterpret_cast<const float4*>(&Vs[j0 + jj][d]);
                    acc[d]     += p * vv.x;
                    acc[d + 1] += p * vv.y;
                    acc[d + 2] += p * vv.z;
                    acc[d + 3] += p * vv.w;
                }
            }
        }
    }

    float inv = 1.f / l;
    float* orow = out + (size_t)(b * T_ + qt) * DIM_ + h * HD_;
    #pragma unroll
    for (int d = 0; d < HD_; d += 4) {
        float4 v = make_float4(acc[d] * inv, acc[d + 1] * inv,
                               acc[d + 2] * inv, acc[d + 3] * inv);
        *reinterpret_cast<float4*>(orow + d) = v;
    }
}

// ---------------------------------------------------------------------------
// kernel_launch
// Inputs (metadata order): x[4,2048,1024] f32, freqs_cos[2048,32] f32,
// freqs_sin[2048,32] f32, mask[4,1,2048,2048] bool (all True, unused),
// Wqkv[1024,3072] f32, Wproj[1024,1024] f32. Output [4,2048,1024] f32.
// ---------------------------------------------------------------------------
extern "C" void kernel_launch(void* const* d_in, const int* in_sizes, int n_in,
                              void* d_out, int out_size)
{
    (void)in_sizes; (void)n_in; (void)out_size;
    const float* x     = (const float*)d_in[0];
    const float* fcos  = (const float*)d_in[1];
    const float* fsin  = (const float*)d_in[2];
    // d_in[3] = mask, all-True, unused
    const float* Wqkv  = (const float*)d_in[4];
    const float* Wproj = (const float*)d_in[5];
    float* out = (float*)d_out;

    float* qkv;  cudaGetSymbolAddress((void**)&qkv,  g_qkv);
    float* attn; cudaGetSymbolAddress((void**)&attn, g_attn);

    // 1) qkv = x @ Wqkv   (8192 x 1024 x 3072)
    {
        dim3 grid(QKV_COLS / BN, NTOK / BM);
        sgemm_kernel<<<grid, 256>>>(NTOK, QKV_COLS, DIM_, x, Wqkv, qkv);
    }
    // 2) attention (RoPE fused) -> attn
    {
        dim3 grid(T_ / BQ, B_ * H_);
        attn_kernel<<<grid, BQ>>>(qkv, fcos, fsin, attn);
    }
    // 3) out = attn @ Wproj  (8192 x 1024 x 1024)
    {
        dim3 grid(DIM_ / BN, NTOK / BM);
        sgemm_kernel<<<grid, 256>>>(NTOK, DIM_, DIM_, attn, Wproj, out);
    }
}

// round 4
// speedup vs baseline: 1.0253x; 1.0253x over previous
#include <cuda_runtime.h>
#include <cuda_bf16.h>
#include <cstdint>

// Problem constants
#define B_   4
#define T_   2048
#define DIM_ 1024
#define H_   16
#define HD_  64
#define NTOK (B_ * T_)          // 8192
#define QKV_COLS (3 * DIM_)     // 3072

// Scratch in device globals (no allocations allowed)
__device__ float g_qkv[(size_t)NTOK * QKV_COLS];     // ~100.7 MB
__device__ float g_attn[(size_t)NTOK * DIM_];        // ~33.5 MB
__device__ float g_wt1[(size_t)QKV_COLS * DIM_];     // Wqkv^T  [3072,1024]
__device__ float g_wt2[(size_t)DIM_ * DIM_];         // Wproj^T [1024,1024]

// ===========================================================================
// mma.sync tf32 helpers (baseline PTX ISA, works on target sm_100)
// ===========================================================================
__device__ __forceinline__ float tf32_hi(float v) {
    return __uint_as_float(__float_as_uint(v) & 0xFFFFE000u);
}
__device__ __forceinline__ float to_tf32f(float v) {
    uint32_t u;
    asm("cvt.rna.tf32.f32 %0, %1;" : "=r"(u) : "f"(v));
    return __uint_as_float(u);
}
// D += A(16x8) * B(8x8), tf32 inputs, f32 accum
__device__ __forceinline__ void mma_tf32(float& d0, float& d1, float& d2, float& d3,
                                         uint32_t a0, uint32_t a1, uint32_t a2, uint32_t a3,
                                         uint32_t b0, uint32_t b1)
{
    asm volatile(
        "mma.sync.aligned.m16n8k8.row.col.f32.tf32.tf32.f32 "
        "{%0,%1,%2,%3}, {%4,%5,%6,%7}, {%8,%9}, {%0,%1,%2,%3};"
        : "+f"(d0), "+f"(d1), "+f"(d2), "+f"(d3)
        : "r"(a0), "r"(a1), "r"(a2), "r"(a3), "r"(b0), "r"(b1));
}

// ===========================================================================
// 3xTF32 GEMM via mma.sync: C[M,N] = A[M,K] @ Bt[N,K]^T
// A row-major (K-contig), Bt row-major (K-contig).
// CTA: 256 threads (8 warps), tile 128x128, K-chunk 32.
// Warp w: rows (w%4)*32 .. +32, cols (w/4)*64 .. +64.
// smem stores hi/lo tiles as (k, k+4) float2 pairs so each mma fragment is
// one LDS.64:  pair index p = ks*4 + (k%8)%4, elem = (k%8)/4.
// Row stride 36 floats (18 float2) to break bank conflicts.
// ===========================================================================
#define GS 36                                   // floats per smem row
#define TILE_FLOATS (128 * GS)                  // 4608
#define GEMM_SMEM_BYTES (4 * TILE_FLOATS * 4)   // AH, AL, BH, BL = 73728 B

__global__ __launch_bounds__(256) void gemm_mma_kernel(
    int M, int N, int K,
    const float* __restrict__ A, const float* __restrict__ Bt,
    float* __restrict__ C)
{
    extern __shared__ float sm[];
    float* AH = sm;
    float* AL = sm + TILE_FLOATS;
    float* BH = sm + 2 * TILE_FLOATS;
    float* BL = sm + 3 * TILE_FLOATS;

    const int tid = threadIdx.x;
    const int wid = tid >> 5;
    const int lid = tid & 31;
    const int gid = lid >> 2;      // groupID (0..7)
    const int tig = lid & 3;       // thread-in-group (0..3)
    const int wm  = (wid & 3) * 32;   // warp row offset in tile
    const int wn  = (wid >> 2) * 64;  // warp col offset in tile

    const float* Ablk = A  + (size_t)blockIdx.y * 128 * K;
    const float* Bblk = Bt + (size_t)blockIdx.x * 128 * K;

    // Per-thread staging assignment: 4 float4 per tensor per chunk.
    // float4 index f = i*256+tid : row = f/8, c4 = (f%8)*4
    float4 ra[4], rb[4];

    auto LOADCH = [&](int c) {
        const int k0 = c * 32;
        #pragma unroll
        for (int i = 0; i < 4; i++) {
            int f = i * 256 + tid;
            int row = f >> 3, c4 = (f & 7) * 4;
            ra[i] = *reinterpret_cast<const float4*>(Ablk + (size_t)row * K + k0 + c4);
            rb[i] = *reinterpret_cast<const float4*>(Bblk + (size_t)row * K + k0 + c4);
        }
    };

    auto STORECH = [&]() {
        #pragma unroll
        for (int i = 0; i < 4; i++) {
            int f = i * 256 + tid;
            int row = f >> 3, c4 = (f & 7) * 4;
            const float* av = reinterpret_cast<const float*>(&ra[i]);
            const float* bv = reinterpret_cast<const float*>(&rb[i]);
            #pragma unroll
            for (int j = 0; j < 4; j++) {
                int k  = c4 + j;                       // 0..31
                int ks = k >> 3, jj = k & 7;
                int pos = row * GS + (ks * 4 + (jj & 3)) * 2 + (jj >> 2);
                float a = av[j];
                float ah = tf32_hi(a);
                AH[pos] = ah;
                AL[pos] = to_tf32f(a - ah);
                float b = bv[j];
                float bh = tf32_hi(b);
                BH[pos] = bh;
                BL[pos] = to_tf32f(b - bh);
            }
        }
    };

    float acc[2][8][4] = {};   // [mtile][ntile][c0..c3]

    const int nch = K / 32;
    LOADCH(0);
    for (int c = 0; c < nch; c++) {
        STORECH();
        __syncthreads();
        if (c + 1 < nch) LOADCH(c + 1);

        #pragma unroll
        for (int ks = 0; ks < 4; ks++) {
            // A fragments: 2 m-tiles x {hi,lo}; each frag = 2 LDS.64
            uint32_t afh[2][4], afl[2][4];
            #pragma unroll
            for (int mt = 0; mt < 2; mt++) {
                int r0 = wm + mt * 16 + gid;
                int p  = (ks * 4 + tig) * 2;
                float2 h0 = *reinterpret_cast<const float2*>(&AH[r0 * GS + p]);
                float2 h1 = *reinterpret_cast<const float2*>(&AH[(r0 + 8) * GS + p]);
                afh[mt][0] = __float_as_uint(h0.x); afh[mt][1] = __float_as_uint(h1.x);
                afh[mt][2] = __float_as_uint(h0.y); afh[mt][3] = __float_as_uint(h1.y);
                float2 l0 = *reinterpret_cast<const float2*>(&AL[r0 * GS + p]);
                float2 l1 = *reinterpret_cast<const float2*>(&AL[(r0 + 8) * GS + p]);
                afl[mt][0] = __float_as_uint(l0.x); afl[mt][1] = __float_as_uint(l1.x);
                afl[mt][2] = __float_as_uint(l0.y); afl[mt][3] = __float_as_uint(l1.y);
            }
            #pragma unroll
            for (int nt = 0; nt < 8; nt++) {
                int n = wn + nt * 8 + gid;
                int p = (ks * 4 + tig) * 2;
                float2 bh = *reinterpret_cast<const float2*>(&BH[n * GS + p]);
                float2 bl = *reinterpret_cast<const float2*>(&BL[n * GS + p]);
                uint32_t bh0 = __float_as_uint(bh.x), bh1 = __float_as_uint(bh.y);
                uint32_t bl0 = __float_as_uint(bl.x), bl1 = __float_as_uint(bl.y);
                #pragma unroll
                for (int mt = 0; mt < 2; mt++) {
                    float* d = acc[mt][nt];
                    mma_tf32(d[0], d[1], d[2], d[3],
                             afh[mt][0], afh[mt][1], afh[mt][2], afh[mt][3], bh0, bh1);
                    mma_tf32(d[0], d[1], d[2], d[3],
                             afh[mt][0], afh[mt][1], afh[mt][2], afh[mt][3], bl0, bl1);
                    mma_tf32(d[0], d[1], d[2], d[3],
                             afl[mt][0], afl[mt][1], afl[mt][2], afl[mt][3], bh0, bh1);
                }
            }
        }
        __syncthreads();
    }

    // Epilogue: c0,c1 at (row, 2*tig), c2,c3 at (row+8, 2*tig)
    float* Cblk = C + (size_t)blockIdx.y * 128 * N + blockIdx.x * 128;
    #pragma unroll
    for (int mt = 0; mt < 2; mt++) {
        #pragma unroll
        for (int nt = 0; nt < 8; nt++) {
            int r = wm + mt * 16 + gid;
            int cn = wn + nt * 8 + tig * 2;
            *reinterpret_cast<float2*>(Cblk + (size_t)r * N + cn) =
                make_float2(acc[mt][nt][0], acc[mt][nt][1]);
            *reinterpret_cast<float2*>(Cblk + (size_t)(r + 8) * N + cn) =
                make_float2(acc[mt][nt][2], acc[mt][nt][3]);
        }
    }
}

// ---------------------------------------------------------------------------
// Transpose: dst[N,K] = src[K,N]^T (both row-major). 32x32 tiles.
// ---------------------------------------------------------------------------
__global__ __launch_bounds__(256) void transpose_kernel(
    const float* __restrict__ src, float* __restrict__ dst, int K, int N)
{
    __shared__ float tile[32][33];
    int n0 = blockIdx.x * 32, k0 = blockIdx.y * 32;
    int tx = threadIdx.x, ty = threadIdx.y;   // block (32,8)
    #pragma unroll
    for (int i = 0; i < 4; i++)
        tile[ty + i * 8][tx] = src[(size_t)(k0 + ty + i * 8) * N + n0 + tx];
    __syncthreads();
    #pragma unroll
    for (int i = 0; i < 4; i++)
        dst[(size_t)(n0 + ty + i * 8) * K + k0 + tx] = tile[tx][ty + i * 8];
}

// ---------------------------------------------------------------------------
// Flash-attention with fused RoPE (validated in R2).
// ---------------------------------------------------------------------------
#define BQ 128
#define BKV 64

__global__ __launch_bounds__(128) void attn_kernel(
    const float* __restrict__ qkv,
    const float* __restrict__ cosT,
    const float* __restrict__ sinT,
    float* __restrict__ out)
{
    const int bh = blockIdx.y;
    const int b  = bh / H_;
    const int h  = bh % H_;
    const int qt = blockIdx.x * BQ + threadIdx.x;

    const float scale = 0.125f;

    const float* qrow = qkv + ((size_t)(b * T_ + qt) * QKV_COLS) + h * HD_;
    float q[HD_];
    #pragma unroll
    for (int i = 0; i < HD_ / 2; i++) {
        float c = cosT[qt * (HD_ / 2) + i];
        float s = sinT[qt * (HD_ / 2) + i];
        float e = qrow[2 * i], o = qrow[2 * i + 1];
        q[2 * i]     = (e * c - o * s) * scale;
        q[2 * i + 1] = (e * s + o * c) * scale;
    }

    float acc[HD_] = {};
    float m = -1e30f, l = 0.f;

    __shared__ float Ks[BKV][HD_];
    __shared__ float Vs[BKV][HD_];

    for (int k0 = 0; k0 < T_; k0 += BKV) {
        __syncthreads();
        #pragma unroll
        for (int i = 0; i < (BKV * HD_) / (128 * 4); i++) {
            int off = (i * 128 + threadIdx.x) * 4;
            int r = off / HD_, c = off % HD_;
            int kt = k0 + r;
            const float* base = qkv + (size_t)(b * T_ + kt) * QKV_COLS + h * HD_ + c;
            float4 kv = *reinterpret_cast<const float4*>(base + DIM_);
            float c0 = cosT[kt * (HD_ / 2) + c / 2];
            float s0 = sinT[kt * (HD_ / 2) + c / 2];
            float c1 = cosT[kt * (HD_ / 2) + c / 2 + 1];
            float s1 = sinT[kt * (HD_ / 2) + c / 2 + 1];
            float4 kr;
            kr.x = kv.x * c0 - kv.y * s0;
            kr.y = kv.x * s0 + kv.y * c0;
            kr.z = kv.z * c1 - kv.w * s1;
            kr.w = kv.z * s1 + kv.w * c1;
            *reinterpret_cast<float4*>(&Ks[r][c]) = kr;
            *reinterpret_cast<float4*>(&Vs[r][c]) =
                *reinterpret_cast<const float4*>(base + 2 * DIM_);
        }
        __syncthreads();

        #pragma unroll 1
        for (int j0 = 0; j0 < BKV; j0 += 16) {
            float sc[16];
            float mt = m;
            #pragma unroll
            for (int jj = 0; jj < 16; jj++) {
                float s = 0.f;
                #pragma unroll
                for (int d = 0; d < HD_; d += 4) {
                    float4 kv = *reinterpret_cast<const float4*>(&Ks[j0 + jj][d]);
                    s += q[d] * kv.x + q[d + 1] * kv.y + q[d + 2] * kv.z + q[d + 3] * kv.w;
                }
                sc[jj] = s;
                mt = fmaxf(mt, s);
            }
            float corr = __expf(m - mt);
            l *= corr;
            #pragma unroll
            for (int d = 0; d < HD_; d++) acc[d] *= corr;
            m = mt;
            #pragma unroll
            for (int jj = 0; jj < 16; jj++) {
                float p = __expf(sc[jj] - mt);
                l += p;
                #pragma unroll
                for (int d = 0; d < HD_; d += 4) {
                    float4 vv = *reinterpret_cast<const float4*>(&Vs[j0 + jj][d]);
                    acc[d]     += p * vv.x;
                    acc[d + 1] += p * vv.y;
                    acc[d + 2] += p * vv.z;
                    acc[d + 3] += p * vv.w;
                }
            }
        }
    }

    float inv = 1.f / l;
    float* orow = out + (size_t)(b * T_ + qt) * DIM_ + h * HD_;
    #pragma unroll
    for (int d = 0; d < HD_; d += 4) {
        float4 v = make_float4(acc[d] * inv, acc[d + 1] * inv,
                               acc[d + 2] * inv, acc[d + 3] * inv);
        *reinterpret_cast<float4*>(orow + d) = v;
    }
}

// ---------------------------------------------------------------------------
// kernel_launch
// ---------------------------------------------------------------------------
extern "C" void kernel_launch(void* const* d_in, const int* in_sizes, int n_in,
                              void* d_out, int out_size)
{
    (void)in_sizes; (void)n_in; (void)out_size;
    const float* x     = (const float*)d_in[0];
    const float* fcos  = (const float*)d_in[1];
    const float* fsin  = (const float*)d_in[2];
    // d_in[3] = mask, all-True, unused
    const float* Wqkv  = (const float*)d_in[4];
    const float* Wproj = (const float*)d_in[5];
    float* out = (float*)d_out;

    float* qkv;  cudaGetSymbolAddress((void**)&qkv,  g_qkv);
    float* attn; cudaGetSymbolAddress((void**)&attn, g_attn);
    float* wt1;  cudaGetSymbolAddress((void**)&wt1,  g_wt1);
    float* wt2;  cudaGetSymbolAddress((void**)&wt2,  g_wt2);

    cudaFuncSetAttribute(gemm_mma_kernel,
                         cudaFuncAttributeMaxDynamicSharedMemorySize, GEMM_SMEM_BYTES);

    // 0) transpose weights to K-major [N,K]
    {
        dim3 blk(32, 8);
        transpose_kernel<<<dim3(QKV_COLS / 32, DIM_ / 32), blk>>>(Wqkv, wt1, DIM_, QKV_COLS);
        transpose_kernel<<<dim3(DIM_ / 32, DIM_ / 32), blk>>>(Wproj, wt2, DIM_, DIM_);
    }
    // 1) qkv = x @ Wqkv   (mma.sync 3xTF32)
    {
        dim3 grid(QKV_COLS / 128, NTOK / 128);
        gemm_mma_kernel<<<grid, 256, GEMM_SMEM_BYTES>>>(NTOK, QKV_COLS, DIM_, x, wt1, qkv);
    }
    // 2) attention (RoPE fused) -> attn
    {
        dim3 grid(T_ / BQ, B_ * H_);
        attn_kernel<<<grid, BQ>>>(qkv, fcos, fsin, attn);
    }
    // 3) out = attn @ Wproj  (mma.sync 3xTF32)
    {
        dim3 grid(DIM_ / 128, NTOK / 128);
        gemm_mma_kernel<<<grid, 256, GEMM_SMEM_BYTES>>>(NTOK, DIM_, DIM_, attn, wt2, out);
    }
}

// round 5
// speedup vs baseline: 1.7799x; 1.7361x over previous
#include <cuda_runtime.h>
#include <cuda_bf16.h>
#include <cstdint>

// Problem constants
#define B_   4
#define T_   2048
#define DIM_ 1024
#define H_   16
#define HD_  64
#define NTOK (B_ * T_)          // 8192
#define QKV_COLS (3 * DIM_)     // 3072

// Scratch in device globals (no allocations allowed)
__device__ float g_qkv[(size_t)NTOK * QKV_COLS];     // ~100.7 MB
__device__ float g_attn[(size_t)NTOK * DIM_];        // ~33.5 MB
__device__ float g_wt1[(size_t)QKV_COLS * DIM_];     // Wqkv^T  [3072,1024]
__device__ float g_wt2[(size_t)DIM_ * DIM_];         // Wproj^T [1024,1024]

// ===========================================================================
// mma.sync helpers (baseline PTX ISA, works on target sm_100)
// ===========================================================================
__device__ __forceinline__ float tf32_hi(float v) {
    return __uint_as_float(__float_as_uint(v) & 0xFFFFE000u);
}
__device__ __forceinline__ float to_tf32f(float v) {
    uint32_t u;
    asm("cvt.rna.tf32.f32 %0, %1;" : "=r"(u) : "f"(v));
    return __uint_as_float(u);
}
// D += A(16x8) * B(8x8), tf32 inputs, f32 accum
__device__ __forceinline__ void mma_tf32(float& d0, float& d1, float& d2, float& d3,
                                         uint32_t a0, uint32_t a1, uint32_t a2, uint32_t a3,
                                         uint32_t b0, uint32_t b1)
{
    asm volatile(
        "mma.sync.aligned.m16n8k8.row.col.f32.tf32.tf32.f32 "
        "{%0,%1,%2,%3}, {%4,%5,%6,%7}, {%8,%9}, {%0,%1,%2,%3};"
        : "+f"(d0), "+f"(d1), "+f"(d2), "+f"(d3)
        : "r"(a0), "r"(a1), "r"(a2), "r"(a3), "r"(b0), "r"(b1));
}
// D += A(16x16) * B(16x8), bf16 inputs, f32 accum
__device__ __forceinline__ void mma_bf16(float* d,
                                         const uint32_t* a, uint32_t b0, uint32_t b1)
{
    asm volatile(
        "mma.sync.aligned.m16n8k16.row.col.f32.bf16.bf16.f32 "
        "{%0,%1,%2,%3}, {%4,%5,%6,%7}, {%8,%9}, {%0,%1,%2,%3};"
        : "+f"(d[0]), "+f"(d[1]), "+f"(d[2]), "+f"(d[3])
        : "r"(a[0]), "r"(a[1]), "r"(a[2]), "r"(a[3]), "r"(b0), "r"(b1));
}
// pack two f32 -> bf16x2 (lo in low half, hi in high half)
__device__ __forceinline__ uint32_t pack_bf16(float lo, float hi) {
    uint32_t r;
    asm("cvt.rn.bf16x2.f32 %0, %1, %2;" : "=r"(r) : "f"(hi), "f"(lo));
    return r;
}
__device__ __forceinline__ float bf16lo_f(uint32_t p) { return __uint_as_float(p << 16); }
__device__ __forceinline__ float bf16hi_f(uint32_t p) { return __uint_as_float(p & 0xFFFF0000u); }
// split pair (v0,v1) -> hi pack + lo pack
__device__ __forceinline__ void split_pair(float v0, float v1, uint32_t& hp, uint32_t& lp) {
    hp = pack_bf16(v0, v1);
    lp = pack_bf16(v0 - bf16lo_f(hp), v1 - bf16hi_f(hp));
}

// ===========================================================================
// 3xTF32 GEMM via mma.sync (validated R4): C[M,N] = A[M,K] @ Bt[N,K]^T
// ===========================================================================
#define GS 36
#define TILE_FLOATS (128 * GS)
#define GEMM_SMEM_BYTES (4 * TILE_FLOATS * 4)

__global__ __launch_bounds__(256) void gemm_mma_kernel(
    int M, int N, int K,
    const float* __restrict__ A, const float* __restrict__ Bt,
    float* __restrict__ C)
{
    extern __shared__ float sm[];
    float* AH = sm;
    float* AL = sm + TILE_FLOATS;
    float* BH = sm + 2 * TILE_FLOATS;
    float* BL = sm + 3 * TILE_FLOATS;

    const int tid = threadIdx.x;
    const int wid = tid >> 5;
    const int lid = tid & 31;
    const int gid = lid >> 2;
    const int tig = lid & 3;
    const int wm  = (wid & 3) * 32;
    const int wn  = (wid >> 2) * 64;

    const float* Ablk = A  + (size_t)blockIdx.y * 128 * K;
    const float* Bblk = Bt + (size_t)blockIdx.x * 128 * K;

    float4 ra[4], rb[4];

    auto LOADCH = [&](int c) {
        const int k0 = c * 32;
        #pragma unroll
        for (int i = 0; i < 4; i++) {
            int f = i * 256 + tid;
            int row = f >> 3, c4 = (f & 7) * 4;
            ra[i] = *reinterpret_cast<const float4*>(Ablk + (size_t)row * K + k0 + c4);
            rb[i] = *reinterpret_cast<const float4*>(Bblk + (size_t)row * K + k0 + c4);
        }
    };
    auto STORECH = [&]() {
        #pragma unroll
        for (int i = 0; i < 4; i++) {
            int f = i * 256 + tid;
            int row = f >> 3, c4 = (f & 7) * 4;
            const float* av = reinterpret_cast<const float*>(&ra[i]);
            const float* bv = reinterpret_cast<const float*>(&rb[i]);
            #pragma unroll
            for (int j = 0; j < 4; j++) {
                int k  = c4 + j;
                int ks = k >> 3, jj = k & 7;
                int pos = row * GS + (ks * 4 + (jj & 3)) * 2 + (jj >> 2);
                float a = av[j];
                float ah = tf32_hi(a);
                AH[pos] = ah;
                AL[pos] = to_tf32f(a - ah);
                float b = bv[j];
                float bh = tf32_hi(b);
                BH[pos] = bh;
                BL[pos] = to_tf32f(b - bh);
            }
        }
    };

    float acc[2][8][4] = {};

    const int nch = K / 32;
    LOADCH(0);
    for (int c = 0; c < nch; c++) {
        STORECH();
        __syncthreads();
        if (c + 1 < nch) LOADCH(c + 1);

        #pragma unroll
        for (int ks = 0; ks < 4; ks++) {
            uint32_t afh[2][4], afl[2][4];
            #pragma unroll
            for (int mt = 0; mt < 2; mt++) {
                int r0 = wm + mt * 16 + gid;
                int p  = (ks * 4 + tig) * 2;
                float2 h0 = *reinterpret_cast<const float2*>(&AH[r0 * GS + p]);
                float2 h1 = *reinterpret_cast<const float2*>(&AH[(r0 + 8) * GS + p]);
                afh[mt][0] = __float_as_uint(h0.x); afh[mt][1] = __float_as_uint(h1.x);
                afh[mt][2] = __float_as_uint(h0.y); afh[mt][3] = __float_as_uint(h1.y);
                float2 l0 = *reinterpret_cast<const float2*>(&AL[r0 * GS + p]);
                float2 l1 = *reinterpret_cast<const float2*>(&AL[(r0 + 8) * GS + p]);
                afl[mt][0] = __float_as_uint(l0.x); afl[mt][1] = __float_as_uint(l1.x);
                afl[mt][2] = __float_as_uint(l0.y); afl[mt][3] = __float_as_uint(l1.y);
            }
            #pragma unroll
            for (int nt = 0; nt < 8; nt++) {
                int n = wn + nt * 8 + gid;
                int p = (ks * 4 + tig) * 2;
                float2 bh = *reinterpret_cast<const float2*>(&BH[n * GS + p]);
                float2 bl = *reinterpret_cast<const float2*>(&BL[n * GS + p]);
                uint32_t bh0 = __float_as_uint(bh.x), bh1 = __float_as_uint(bh.y);
                uint32_t bl0 = __float_as_uint(bl.x), bl1 = __float_as_uint(bl.y);
                #pragma unroll
                for (int mt = 0; mt < 2; mt++) {
                    float* d = acc[mt][nt];
                    mma_tf32(d[0], d[1], d[2], d[3],
                             afh[mt][0], afh[mt][1], afh[mt][2], afh[mt][3], bh0, bh1);
                    mma_tf32(d[0], d[1], d[2], d[3],
                             afh[mt][0], afh[mt][1], afh[mt][2], afh[mt][3], bl0, bl1);
                    mma_tf32(d[0], d[1], d[2], d[3],
                             afl[mt][0], afl[mt][1], afl[mt][2], afl[mt][3], bh0, bh1);
                }
            }
        }
        __syncthreads();
    }

    float* Cblk = C + (size_t)blockIdx.y * 128 * N + blockIdx.x * 128;
    #pragma unroll
    for (int mt = 0; mt < 2; mt++) {
        #pragma unroll
        for (int nt = 0; nt < 8; nt++) {
            int r = wm + mt * 16 + gid;
            int cn = wn + nt * 8 + tig * 2;
            *reinterpret_cast<float2*>(Cblk + (size_t)r * N + cn) =
                make_float2(acc[mt][nt][0], acc[mt][nt][1]);
            *reinterpret_cast<float2*>(Cblk + (size_t)(r + 8) * N + cn) =
                make_float2(acc[mt][nt][2], acc[mt][nt][3]);
        }
    }
}

// ---------------------------------------------------------------------------
// Transpose: dst[N,K] = src[K,N]^T.
// ---------------------------------------------------------------------------
__global__ __launch_bounds__(256) void transpose_kernel(
    const float* __restrict__ src, float* __restrict__ dst, int K, int N)
{
    __shared__ float tile[32][33];
    int n0 = blockIdx.x * 32, k0 = blockIdx.y * 32;
    int tx = threadIdx.x, ty = threadIdx.y;
    #pragma unroll
    for (int i = 0; i < 4; i++)
        tile[ty + i * 8][tx] = src[(size_t)(k0 + ty + i * 8) * N + n0 + tx];
    __syncthreads();
    #pragma unroll
    for (int i = 0; i < 4; i++)
        dst[(size_t)(n0 + ty + i * 8) * K + k0 + tx] = tile[tx][ty + i * 8];
}

// ===========================================================================
// Tensor-core flash attention (bf16x3 via m16n8k16), RoPE fused.
// Block = 128 queries x one (b,h); 8 warps, each warp m16 queries.
// KV tiles of 64 keys; K staged [key][dim] bf16 hi/lo; V staged transposed
// [dim][key] bf16 hi/lo. Row stride 36 words -> conflict-free frag loads.
// ===========================================================================
#define KSTRW 36    // uint32 words per smem row (72 bf16)

__global__ __launch_bounds__(256) void attn_mma_kernel(
    const float* __restrict__ qkv,
    const float* __restrict__ cosT,
    const float* __restrict__ sinT,
    float* __restrict__ out)
{
    __shared__ uint32_t Kh[64 * KSTRW], Kl[64 * KSTRW];
    __shared__ uint32_t Vh[64 * KSTRW], Vl[64 * KSTRW];

    const int bh = blockIdx.y;
    const int b  = bh >> 4;
    const int h  = bh & 15;
    const int tid = threadIdx.x;
    const int wid = tid >> 5;
    const int lid = tid & 31;
    const int gid = lid >> 2;
    const int tig = lid & 3;

    const int r0 = blockIdx.x * 128 + wid * 16 + gid;   // query rows
    const int r1 = r0 + 8;
    const float scale = 0.125f;

    // --- Q fragments (RoPE + scale + bf16 hi/lo split), loaded once ---
    uint32_t QH[4][4], QL[4][4];
    #pragma unroll
    for (int ks = 0; ks < 4; ks++) {
        #pragma unroll
        for (int j = 0; j < 4; j++) {
            int row  = (j & 1) ? r1 : r0;
            int dim0 = ks * 16 + (j >> 1) * 8 + 2 * tig;
            const float* qp = qkv + (size_t)(b * T_ + row) * QKV_COLS + h * HD_ + dim0;
            float2 q = *reinterpret_cast<const float2*>(qp);
            float c = cosT[row * (HD_ / 2) + dim0 / 2];
            float s = sinT[row * (HD_ / 2) + dim0 / 2];
            float v0 = (q.x * c - q.y * s) * scale;
            float v1 = (q.x * s + q.y * c) * scale;
            split_pair(v0, v1, QH[ks][j], QL[ks][j]);
        }
    }

    float O[8][4] = {};
    float m0 = -1e30f, m1 = -1e30f, l0 = 0.f, l1 = 0.f;

    for (int k0 = 0; k0 < T_; k0 += 64) {
        // ---- stage K (RoPE) and V (transposed), bf16 hi/lo ----
        #pragma unroll
        for (int i = 0; i < 4; i++) {
            int off4 = i * 256 + tid;       // 0..1023
            int key  = off4 >> 4;
            int dp   = (off4 & 15) * 4;
            int kt   = k0 + key;
            const float* base = qkv + (size_t)(b * T_ + kt) * QKV_COLS + h * HD_ + dp;
            // K with RoPE
            float4 kv = *reinterpret_cast<const float4*>(base + DIM_);
            float c0 = cosT[kt * (HD_ / 2) + dp / 2];
            float s0 = sinT[kt * (HD_ / 2) + dp / 2];
            float c1 = cosT[kt * (HD_ / 2) + dp / 2 + 1];
            float s1 = sinT[kt * (HD_ / 2) + dp / 2 + 1];
            float k0r = kv.x * c0 - kv.y * s0;
            float k1r = kv.x * s0 + kv.y * c0;
            float k2r = kv.z * c1 - kv.w * s1;
            float k3r = kv.z * s1 + kv.w * c1;
            uint32_t hp, lp;
            split_pair(k0r, k1r, hp, lp);
            Kh[key * KSTRW + dp / 2] = hp;
            Kl[key * KSTRW + dp / 2] = lp;
            split_pair(k2r, k3r, hp, lp);
            Kh[key * KSTRW + dp / 2 + 1] = hp;
            Kl[key * KSTRW + dp / 2 + 1] = lp;
            // V transposed: Vt[dim][key]
            float4 vv = *reinterpret_cast<const float4*>(base + 2 * DIM_);
            const float ve[4] = {vv.x, vv.y, vv.z, vv.w};
            #pragma unroll
            for (int j = 0; j < 4; j++) {
                __nv_bfloat16 vhi = __float2bfloat16(ve[j]);
                float vlo = ve[j] - __bfloat162float(vhi);
                reinterpret_cast<__nv_bfloat16*>(Vh)[(dp + j) * (2 * KSTRW) + key] = vhi;
                reinterpret_cast<__nv_bfloat16*>(Vl)[(dp + j) * (2 * KSTRW) + key] =
                    __float2bfloat16(vlo);
            }
        }
        __syncthreads();

        // ---- S = Q K^T (bf16x3) ----
        float S[8][4] = {};
        #pragma unroll
        for (int ks = 0; ks < 4; ks++) {
            #pragma unroll
            for (int nt = 0; nt < 8; nt++) {
                int key = nt * 8 + gid;
                uint32_t bh0 = Kh[key * KSTRW + ks * 8 + tig];
                uint32_t bh1 = Kh[key * KSTRW + ks * 8 + 4 + tig];
                uint32_t bl0 = Kl[key * KSTRW + ks * 8 + tig];
                uint32_t bl1 = Kl[key * KSTRW + ks * 8 + 4 + tig];
                mma_bf16(S[nt], QH[ks], bh0, bh1);
                mma_bf16(S[nt], QH[ks], bl0, bl1);
                mma_bf16(S[nt], QL[ks], bh0, bh1);
            }
        }

        // ---- online softmax ----
        float mt0 = m0, mt1 = m1;
        #pragma unroll
        for (int nt = 0; nt < 8; nt++) {
            mt0 = fmaxf(mt0, fmaxf(S[nt][0], S[nt][1]));
            mt1 = fmaxf(mt1, fmaxf(S[nt][2], S[nt][3]));
        }
        mt0 = fmaxf(mt0, __shfl_xor_sync(0xFFFFFFFFu, mt0, 1));
        mt0 = fmaxf(mt0, __shfl_xor_sync(0xFFFFFFFFu, mt0, 2));
        mt1 = fmaxf(mt1, __shfl_xor_sync(0xFFFFFFFFu, mt1, 1));
        mt1 = fmaxf(mt1, __shfl_xor_sync(0xFFFFFFFFu, mt1, 2));
        float cr0 = __expf(m0 - mt0), cr1 = __expf(m1 - mt1);
        m0 = mt0; m1 = mt1;
        float rs0 = 0.f, rs1 = 0.f;
        #pragma unroll
        for (int nt = 0; nt < 8; nt++) {
            S[nt][0] = __expf(S[nt][0] - m0);
            S[nt][1] = __expf(S[nt][1] - m0);
            S[nt][2] = __expf(S[nt][2] - m1);
            S[nt][3] = __expf(S[nt][3] - m1);
            rs0 += S[nt][0] + S[nt][1];
            rs1 += S[nt][2] + S[nt][3];
        }
        rs0 += __shfl_xor_sync(0xFFFFFFFFu, rs0, 1);
        rs0 += __shfl_xor_sync(0xFFFFFFFFu, rs0, 2);
        rs1 += __shfl_xor_sync(0xFFFFFFFFu, rs1, 1);
        rs1 += __shfl_xor_sync(0xFFFFFFFFu, rs1, 2);
        l0 = l0 * cr0 + rs0;
        l1 = l1 * cr1 + rs1;
        #pragma unroll
        for (int nt = 0; nt < 8; nt++) {
            O[nt][0] *= cr0; O[nt][1] *= cr0;
            O[nt][2] *= cr1; O[nt][3] *= cr1;
        }

        // ---- O += P V (bf16x3); P fragments packed from S registers ----
        #pragma unroll
        for (int ks = 0; ks < 4; ks++) {
            uint32_t pH[4], pL[4];
            split_pair(S[2 * ks][0],     S[2 * ks][1],     pH[0], pL[0]);
            split_pair(S[2 * ks][2],     S[2 * ks][3],     pH[1], pL[1]);
            split_pair(S[2 * ks + 1][0], S[2 * ks + 1][1], pH[2], pL[2]);
            split_pair(S[2 * ks + 1][2], S[2 * ks + 1][3], pH[3], pL[3]);
            #pragma unroll
            for (int nt = 0; nt < 8; nt++) {
                int dim = nt * 8 + gid;
                uint32_t bh0 = Vh[dim * KSTRW + ks * 8 + tig];
                uint32_t bh1 = Vh[dim * KSTRW + ks * 8 + 4 + tig];
                uint32_t bl0 = Vl[dim * KSTRW + ks * 8 + tig];
                uint32_t bl1 = Vl[dim * KSTRW + ks * 8 + 4 + tig];
                mma_bf16(O[nt], pH, bh0, bh1);
                mma_bf16(O[nt], pH, bl0, bl1);
                mma_bf16(O[nt], pL, bh0, bh1);
            }
        }
        __syncthreads();
    }

    // ---- finalize + write ----
    float i0 = 1.f / l0, i1 = 1.f / l1;
    float* o0 = out + (size_t)(b * T_ + r0) * DIM_ + h * HD_;
    float* o1 = out + (size_t)(b * T_ + r1) * DIM_ + h * HD_;
    #pragma unroll
    for (int nt = 0; nt < 8; nt++) {
        int cn = nt * 8 + 2 * tig;
        *reinterpret_cast<float2*>(o0 + cn) = make_float2(O[nt][0] * i0, O[nt][1] * i0);
        *reinterpret_cast<float2*>(o1 + cn) = make_float2(O[nt][2] * i1, O[nt][3] * i1);
    }
}

// ---------------------------------------------------------------------------
// kernel_launch
// ---------------------------------------------------------------------------
extern "C" void kernel_launch(void* const* d_in, const int* in_sizes, int n_in,
                              void* d_out, int out_size)
{
    (void)in_sizes; (void)n_in; (void)out_size;
    const float* x     = (const float*)d_in[0];
    const float* fcos  = (const float*)d_in[1];
    const float* fsin  = (const float*)d_in[2];
    // d_in[3] = mask, all-True, unused
    const float* Wqkv  = (const float*)d_in[4];
    const float* Wproj = (const float*)d_in[5];
    float* out = (float*)d_out;

    float* qkv;  cudaGetSymbolAddress((void**)&qkv,  g_qkv);
    float* attn; cudaGetSymbolAddress((void**)&attn, g_attn);
    float* wt1;  cudaGetSymbolAddress((void**)&wt1,  g_wt1);
    float* wt2;  cudaGetSymbolAddress((void**)&wt2,  g_wt2);

    cudaFuncSetAttribute(gemm_mma_kernel,
                         cudaFuncAttributeMaxDynamicSharedMemorySize, GEMM_SMEM_BYTES);

    // 0) transpose weights to K-major [N,K]
    {
        dim3 blk(32, 8);
        transpose_kernel<<<dim3(QKV_COLS / 32, DIM_ / 32), blk>>>(Wqkv, wt1, DIM_, QKV_COLS);
        transpose_kernel<<<dim3(DIM_ / 32, DIM_ / 32), blk>>>(Wproj, wt2, DIM_, DIM_);
    }
    // 1) qkv = x @ Wqkv   (mma.sync 3xTF32)
    {
        dim3 grid(QKV_COLS / 128, NTOK / 128);
        gemm_mma_kernel<<<grid, 256, GEMM_SMEM_BYTES>>>(NTOK, QKV_COLS, DIM_, x, wt1, qkv);
    }
    // 2) attention (RoPE fused, tensor-core) -> attn
    {
        dim3 grid(T_ / 128, B_ * H_);
        attn_mma_kernel<<<grid, 256>>>(qkv, fcos, fsin, attn);
    }
    // 3) out = attn @ Wproj  (mma.sync 3xTF32)
    {
        dim3 grid(DIM_ / 128, NTOK / 128);
        gemm_mma_kernel<<<grid, 256, GEMM_SMEM_BYTES>>>(NTOK, DIM_, DIM_, attn, wt2, out);
    }
}

// round 6
// speedup vs baseline: 2.7484x; 1.5441x over previous
#include <cuda_runtime.h>
#include <cuda_bf16.h>
#include <cstdint>

// Problem constants
#define B_   4
#define T_   2048
#define DIM_ 1024
#define H_   16
#define HD_  64
#define NTOK (B_ * T_)          // 8192
#define QKV_COLS (3 * DIM_)     // 3072

// Scratch in device globals (no allocations allowed)
__device__ float g_qkv[(size_t)NTOK * QKV_COLS];     // ~100.7 MB
__device__ float g_attn[(size_t)NTOK * DIM_];        // ~33.5 MB
__device__ float g_wt1[(size_t)QKV_COLS * DIM_];     // Wqkv^T  [3072,1024]
__device__ float g_wt2[(size_t)DIM_ * DIM_];         // Wproj^T [1024,1024]

// ===========================================================================
// mma.sync helpers (baseline PTX ISA, works on target sm_100)
// ===========================================================================
// D += A(16x16) * B(16x8), bf16 inputs, f32 accum
__device__ __forceinline__ void mma_bf16(float* d,
                                         const uint32_t* a, uint32_t b0, uint32_t b1)
{
    asm volatile(
        "mma.sync.aligned.m16n8k16.row.col.f32.bf16.bf16.f32 "
        "{%0,%1,%2,%3}, {%4,%5,%6,%7}, {%8,%9}, {%0,%1,%2,%3};"
        : "+f"(d[0]), "+f"(d[1]), "+f"(d[2]), "+f"(d[3])
        : "r"(a[0]), "r"(a[1]), "r"(a[2]), "r"(a[3]), "r"(b0), "r"(b1));
}
// pack two f32 -> bf16x2 (v0 in low half, v1 in high half)
__device__ __forceinline__ uint32_t pack_bf16(float lo, float hi) {
    uint32_t r;
    asm("cvt.rn.bf16x2.f32 %0, %1, %2;" : "=r"(r) : "f"(hi), "f"(lo));
    return r;
}
__device__ __forceinline__ float bf16lo_f(uint32_t p) { return __uint_as_float(p << 16); }
__device__ __forceinline__ float bf16hi_f(uint32_t p) { return __uint_as_float(p & 0xFFFF0000u); }
// split pair (v0,v1) -> hi pack + lo pack
__device__ __forceinline__ void split_pair(float v0, float v1, uint32_t& hp, uint32_t& lp) {
    hp = pack_bf16(v0, v1);
    lp = pack_bf16(v0 - bf16lo_f(hp), v1 - bf16hi_f(hp));
}

// ===========================================================================
// bf16x3 GEMM via m16n8k16: C[M,N] = A[M,K] @ Bt[N,K]^T
// A row-major (K-contig), Bt row-major (K-contig).
// CTA: 256 threads (8 warps), tile 128x128, K-chunk 64.
// Warp w: rows (w%4)*32, cols (w/4)*64. smem tiles hold bf16x2 words along k
// (word i = k 2i,2i+1); row stride 36 words. Fragment loads: word tig and
// tig+4 of each 8-word k16 group — same layout validated in attn_mma_kernel.
// ===========================================================================
#define GW 36                                   // uint32 words per smem row
#define TILE_WORDS (128 * GW)                   // 4608
#define GEMM_SMEM_BYTES (4 * TILE_WORDS * 4)    // AH, AL, BH, BL = 73728 B

__global__ __launch_bounds__(256) void gemm_bf16_kernel(
    int M, int N, int K,
    const float* __restrict__ A, const float* __restrict__ Bt,
    float* __restrict__ C)
{
    extern __shared__ uint32_t smw[];
    uint32_t* AH = smw;
    uint32_t* AL = smw + TILE_WORDS;
    uint32_t* BH = smw + 2 * TILE_WORDS;
    uint32_t* BL = smw + 3 * TILE_WORDS;

    const int tid = threadIdx.x;
    const int wid = tid >> 5;
    const int lid = tid & 31;
    const int gid = lid >> 2;      // 0..7
    const int tig = lid & 3;       // 0..3
    const int wm  = (wid & 3) * 32;
    const int wn  = (wid >> 2) * 64;

    const float* Ablk = A  + (size_t)blockIdx.y * 128 * K;
    const float* Bblk = Bt + (size_t)blockIdx.x * 128 * K;

    // Per-chunk staging: 128 rows x 64 floats per tensor = 2048 float4;
    // 8 float4 per thread per tensor.
    float4 ra[8], rb[8];

    auto LOADCH = [&](int c) {
        const int k0 = c * 64;
        #pragma unroll
        for (int i = 0; i < 8; i++) {
            int f = i * 256 + tid;
            int row = f >> 4, c4 = (f & 15) * 4;
            ra[i] = *reinterpret_cast<const float4*>(Ablk + (size_t)row * K + k0 + c4);
            rb[i] = *reinterpret_cast<const float4*>(Bblk + (size_t)row * K + k0 + c4);
        }
    };
    auto STORECH = [&]() {
        #pragma unroll
        for (int i = 0; i < 8; i++) {
            int f = i * 256 + tid;
            int row = f >> 4, c4 = (f & 15) * 4;
            int base = row * GW + (c4 >> 1);
            uint32_t hp, lp;
            split_pair(ra[i].x, ra[i].y, hp, lp);
            AH[base] = hp; AL[base] = lp;
            split_pair(ra[i].z, ra[i].w, hp, lp);
            AH[base + 1] = hp; AL[base + 1] = lp;
            split_pair(rb[i].x, rb[i].y, hp, lp);
            BH[base] = hp; BL[base] = lp;
            split_pair(rb[i].z, rb[i].w, hp, lp);
            BH[base + 1] = hp; BL[base + 1] = lp;
        }
    };

    float acc[2][8][4] = {};   // [mtile][ntile][c0..c3]

    const int nch = K / 64;
    LOADCH(0);
    for (int c = 0; c < nch; c++) {
        STORECH();
        __syncthreads();
        if (c + 1 < nch) LOADCH(c + 1);

        #pragma unroll
        for (int ks = 0; ks < 4; ks++) {      // 4 k16 steps per chunk
            uint32_t afh[2][4], afl[2][4];
            #pragma unroll
            for (int mt = 0; mt < 2; mt++) {
                int r0 = wm + mt * 16 + gid;
                int p  = ks * 8;
                afh[mt][0] = AH[r0 * GW + p + tig];
                afh[mt][1] = AH[(r0 + 8) * GW + p + tig];
                afh[mt][2] = AH[r0 * GW + p + 4 + tig];
                afh[mt][3] = AH[(r0 + 8) * GW + p + 4 + tig];
                afl[mt][0] = AL[r0 * GW + p + tig];
                afl[mt][1] = AL[(r0 + 8) * GW + p + tig];
                afl[mt][2] = AL[r0 * GW + p + 4 + tig];
                afl[mt][3] = AL[(r0 + 8) * GW + p + 4 + tig];
            }
            #pragma unroll
            for (int nt = 0; nt < 8; nt++) {
                int n = wn + nt * 8 + gid;
                int p = ks * 8;
                uint32_t bh0 = BH[n * GW + p + tig];
                uint32_t bh1 = BH[n * GW + p + 4 + tig];
                uint32_t bl0 = BL[n * GW + p + tig];
                uint32_t bl1 = BL[n * GW + p + 4 + tig];
                #pragma unroll
                for (int mt = 0; mt < 2; mt++) {
                    float* d = acc[mt][nt];
                    mma_bf16(d, afh[mt], bh0, bh1);
                    mma_bf16(d, afh[mt], bl0, bl1);
                    mma_bf16(d, afl[mt], bh0, bh1);
                }
            }
        }
        __syncthreads();
    }

    // Epilogue: c0,c1 at (row, 2*tig), c2,c3 at (row+8, 2*tig)
    float* Cblk = C + (size_t)blockIdx.y * 128 * N + blockIdx.x * 128;
    #pragma unroll
    for (int mt = 0; mt < 2; mt++) {
        #pragma unroll
        for (int nt = 0; nt < 8; nt++) {
            int r = wm + mt * 16 + gid;
            int cn = wn + nt * 8 + tig * 2;
            *reinterpret_cast<float2*>(Cblk + (size_t)r * N + cn) =
                make_float2(acc[mt][nt][0], acc[mt][nt][1]);
            *reinterpret_cast<float2*>(Cblk + (size_t)(r + 8) * N + cn) =
                make_float2(acc[mt][nt][2], acc[mt][nt][3]);
        }
    }
}

// ---------------------------------------------------------------------------
// Transpose: dst[N,K] = src[K,N]^T.
// ---------------------------------------------------------------------------
__global__ __launch_bounds__(256) void transpose_kernel(
    const float* __restrict__ src, float* __restrict__ dst, int K, int N)
{
    __shared__ float tile[32][33];
    int n0 = blockIdx.x * 32, k0 = blockIdx.y * 32;
    int tx = threadIdx.x, ty = threadIdx.y;
    #pragma unroll
    for (int i = 0; i < 4; i++)
        tile[ty + i * 8][tx] = src[(size_t)(k0 + ty + i * 8) * N + n0 + tx];
    __syncthreads();
    #pragma unroll
    for (int i = 0; i < 4; i++)
        dst[(size_t)(n0 + ty + i * 8) * K + k0 + tx] = tile[tx][ty + i * 8];
}

// ===========================================================================
// Tensor-core flash attention (bf16x3 via m16n8k16), RoPE fused. (R5, passing)
// ===========================================================================
#define KSTRW 36    // uint32 words per smem row

__global__ __launch_bounds__(256) void attn_mma_kernel(
    const float* __restrict__ qkv,
    const float* __restrict__ cosT,
    const float* __restrict__ sinT,
    float* __restrict__ out)
{
    __shared__ uint32_t Kh[64 * KSTRW], Kl[64 * KSTRW];
    __shared__ uint32_t Vh[64 * KSTRW], Vl[64 * KSTRW];

    const int bh = blockIdx.y;
    const int b  = bh >> 4;
    const int h  = bh & 15;
    const int tid = threadIdx.x;
    const int wid = tid >> 5;
    const int lid = tid & 31;
    const int gid = lid >> 2;
    const int tig = lid & 3;

    const int r0 = blockIdx.x * 128 + wid * 16 + gid;
    const int r1 = r0 + 8;
    const float scale = 0.125f;

    uint32_t QH[4][4], QL[4][4];
    #pragma unroll
    for (int ks = 0; ks < 4; ks++) {
        #pragma unroll
        for (int j = 0; j < 4; j++) {
            int row  = (j & 1) ? r1 : r0;
            int dim0 = ks * 16 + (j >> 1) * 8 + 2 * tig;
            const float* qp = qkv + (size_t)(b * T_ + row) * QKV_COLS + h * HD_ + dim0;
            float2 q = *reinterpret_cast<const float2*>(qp);
            float c = cosT[row * (HD_ / 2) + dim0 / 2];
            float s = sinT[row * (HD_ / 2) + dim0 / 2];
            float v0 = (q.x * c - q.y * s) * scale;
            float v1 = (q.x * s + q.y * c) * scale;
            split_pair(v0, v1, QH[ks][j], QL[ks][j]);
        }
    }

    float O[8][4] = {};
    float m0 = -1e30f, m1 = -1e30f, l0 = 0.f, l1 = 0.f;

    for (int k0 = 0; k0 < T_; k0 += 64) {
        #pragma unroll
        for (int i = 0; i < 4; i++) {
            int off4 = i * 256 + tid;
            int key  = off4 >> 4;
            int dp   = (off4 & 15) * 4;
            int kt   = k0 + key;
            const float* base = qkv + (size_t)(b * T_ + kt) * QKV_COLS + h * HD_ + dp;
            float4 kv = *reinterpret_cast<const float4*>(base + DIM_);
            float c0 = cosT[kt * (HD_ / 2) + dp / 2];
            float s0 = sinT[kt * (HD_ / 2) + dp / 2];
            float c1 = cosT[kt * (HD_ / 2) + dp / 2 + 1];
            float s1 = sinT[kt * (HD_ / 2) + dp / 2 + 1];
            float k0r = kv.x * c0 - kv.y * s0;
            float k1r = kv.x * s0 + kv.y * c0;
            float k2r = kv.z * c1 - kv.w * s1;
            float k3r = kv.z * s1 + kv.w * c1;
            uint32_t hp, lp;
            split_pair(k0r, k1r, hp, lp);
            Kh[key * KSTRW + dp / 2] = hp;
            Kl[key * KSTRW + dp / 2] = lp;
            split_pair(k2r, k3r, hp, lp);
            Kh[key * KSTRW + dp / 2 + 1] = hp;
            Kl[key * KSTRW + dp / 2 + 1] = lp;
            float4 vv = *reinterpret_cast<const float4*>(base + 2 * DIM_);
            const float ve[4] = {vv.x, vv.y, vv.z, vv.w};
            #pragma unroll
            for (int j = 0; j < 4; j++) {
                __nv_bfloat16 vhi = __float2bfloat16(ve[j]);
                float vlo = ve[j] - __bfloat162float(vhi);
                reinterpret_cast<__nv_bfloat16*>(Vh)[(dp + j) * (2 * KSTRW) + key] = vhi;
                reinterpret_cast<__nv_bfloat16*>(Vl)[(dp + j) * (2 * KSTRW) + key] =
                    __float2bfloat16(vlo);
            }
        }
        __syncthreads();

        float S[8][4] = {};
        #pragma unroll
        for (int ks = 0; ks < 4; ks++) {
            #pragma unroll
            for (int nt = 0; nt < 8; nt++) {
                int key = nt * 8 + gid;
                uint32_t bh0 = Kh[key * KSTRW + ks * 8 + tig];
                uint32_t bh1 = Kh[key * KSTRW + ks * 8 + 4 + tig];
                uint32_t bl0 = Kl[key * KSTRW + ks * 8 + tig];
                uint32_t bl1 = Kl[key * KSTRW + ks * 8 + 4 + tig];
                mma_bf16(S[nt], QH[ks], bh0, bh1);
                mma_bf16(S[nt], QH[ks], bl0, bl1);
                mma_bf16(S[nt], QL[ks], bh0, bh1);
            }
        }

        float mt0 = m0, mt1 = m1;
        #pragma unroll
        for (int nt = 0; nt < 8; nt++) {
            mt0 = fmaxf(mt0, fmaxf(S[nt][0], S[nt][1]));
            mt1 = fmaxf(mt1, fmaxf(S[nt][2], S[nt][3]));
        }
        mt0 = fmaxf(mt0, __shfl_xor_sync(0xFFFFFFFFu, mt0, 1));
        mt0 = fmaxf(mt0, __shfl_xor_sync(0xFFFFFFFFu, mt0, 2));
        mt1 = fmaxf(mt1, __shfl_xor_sync(0xFFFFFFFFu, mt1, 1));
        mt1 = fmaxf(mt1, __shfl_xor_sync(0xFFFFFFFFu, mt1, 2));
        float cr0 = __expf(m0 - mt0), cr1 = __expf(m1 - mt1);
        m0 = mt0; m1 = mt1;
        float rs0 = 0.f, rs1 = 0.f;
        #pragma unroll
        for (int nt = 0; nt < 8; nt++) {
            S[nt][0] = __expf(S[nt][0] - m0);
            S[nt][1] = __expf(S[nt][1] - m0);
            S[nt][2] = __expf(S[nt][2] - m1);
            S[nt][3] = __expf(S[nt][3] - m1);
            rs0 += S[nt][0] + S[nt][1];
            rs1 += S[nt][2] + S[nt][3];
        }
        rs0 += __shfl_xor_sync(0xFFFFFFFFu, rs0, 1);
        rs0 += __shfl_xor_sync(0xFFFFFFFFu, rs0, 2);
        rs1 += __shfl_xor_sync(0xFFFFFFFFu, rs1, 1);
        rs1 += __shfl_xor_sync(0xFFFFFFFFu, rs1, 2);
        l0 = l0 * cr0 + rs0;
        l1 = l1 * cr1 + rs1;
        #pragma unroll
        for (int nt = 0; nt < 8; nt++) {
            O[nt][0] *= cr0; O[nt][1] *= cr0;
            O[nt][2] *= cr1; O[nt][3] *= cr1;
        }

        #pragma unroll
        for (int ks = 0; ks < 4; ks++) {
            uint32_t pH[4], pL[4];
            split_pair(S[2 * ks][0],     S[2 * ks][1],     pH[0], pL[0]);
            split_pair(S[2 * ks][2],     S[2 * ks][3],     pH[1], pL[1]);
            split_pair(S[2 * ks + 1][0], S[2 * ks + 1][1], pH[2], pL[2]);
            split_pair(S[2 * ks + 1][2], S[2 * ks + 1][3], pH[3], pL[3]);
            #pragma unroll
            for (int nt = 0; nt < 8; nt++) {
                int dim = nt * 8 + gid;
                uint32_t bh0 = Vh[dim * KSTRW + ks * 8 + tig];
                uint32_t bh1 = Vh[dim * KSTRW + ks * 8 + 4 + tig];
                uint32_t bl0 = Vl[dim * KSTRW + ks * 8 + tig];
                uint32_t bl1 = Vl[dim * KSTRW + ks * 8 + 4 + tig];
                mma_bf16(O[nt], pH, bh0, bh1);
                mma_bf16(O[nt], pH, bl0, bl1);
                mma_bf16(O[nt], pL, bh0, bh1);
            }
        }
        __syncthreads();
    }

    float i0 = 1.f / l0, i1 = 1.f / l1;
    float* o0 = out + (size_t)(b * T_ + r0) * DIM_ + h * HD_;
    float* o1 = out + (size_t)(b * T_ + r1) * DIM_ + h * HD_;
    #pragma unroll
    for (int nt = 0; nt < 8; nt++) {
        int cn = nt * 8 + 2 * tig;
        *reinterpret_cast<float2*>(o0 + cn) = make_float2(O[nt][0] * i0, O[nt][1] * i0);
        *reinterpret_cast<float2*>(o1 + cn) = make_float2(O[nt][2] * i1, O[nt][3] * i1);
    }
}

// ---------------------------------------------------------------------------
// kernel_launch
// ---------------------------------------------------------------------------
extern "C" void kernel_launch(void* const* d_in, const int* in_sizes, int n_in,
                              void* d_out, int out_size)
{
    (void)in_sizes; (void)n_in; (void)out_size;
    const float* x     = (const float*)d_in[0];
    const float* fcos  = (const float*)d_in[1];
    const float* fsin  = (const float*)d_in[2];
    // d_in[3] = mask, all-True, unused
    const float* Wqkv  = (const float*)d_in[4];
    const float* Wproj = (const float*)d_in[5];
    float* out = (float*)d_out;

    float* qkv;  cudaGetSymbolAddress((void**)&qkv,  g_qkv);
    float* attn; cudaGetSymbolAddress((void**)&attn, g_attn);
    float* wt1;  cudaGetSymbolAddress((void**)&wt1,  g_wt1);
    float* wt2;  cudaGetSymbolAddress((void**)&wt2,  g_wt2);

    cudaFuncSetAttribute(gemm_bf16_kernel,
                         cudaFuncAttributeMaxDynamicSharedMemorySize, GEMM_SMEM_BYTES);

    // 0) transpose weights to K-major [N,K]
    {
        dim3 blk(32, 8);
        transpose_kernel<<<dim3(QKV_COLS / 32, DIM_ / 32), blk>>>(Wqkv, wt1, DIM_, QKV_COLS);
        transpose_kernel<<<dim3(DIM_ / 32, DIM_ / 32), blk>>>(Wproj, wt2, DIM_, DIM_);
    }
    // 1) qkv = x @ Wqkv   (mma.sync bf16x3)
    {
        dim3 grid(QKV_COLS / 128, NTOK / 128);
        gemm_bf16_kernel<<<grid, 256, GEMM_SMEM_BYTES>>>(NTOK, QKV_COLS, DIM_, x, wt1, qkv);
    }
    // 2) attention (RoPE fused, tensor-core) -> attn
    {
        dim3 grid(T_ / 128, B_ * H_);
        attn_mma_kernel<<<grid, 256>>>(qkv, fcos, fsin, attn);
    }
    // 3) out = attn @ Wproj  (mma.sync bf16x3)
    {
        dim3 grid(DIM_ / 128, NTOK / 128);
        gemm_bf16_kernel<<<grid, 256, GEMM_SMEM_BYTES>>>(NTOK, DIM_, DIM_, attn, wt2, out);
    }
}

// round 8
// speedup vs baseline: 3.3308x; 1.2119x over previous
#include <cuda_runtime.h>
#include <cuda_bf16.h>
#include <cstdint>

// Problem constants
#define B_   4
#define T_   2048
#define DIM_ 1024
#define H_   16
#define HD_  64
#define NTOK (B_ * T_)          // 8192
#define QKV_COLS (3 * DIM_)     // 3072
#define BH_  (B_ * H_)          // 64

// Scratch in device globals (no allocations allowed)
__device__ float g_qkv[(size_t)NTOK * QKV_COLS];     // ~100.7 MB
__device__ float g_attn[(size_t)NTOK * DIM_];        // ~33.5 MB
__device__ float g_wt1[(size_t)QKV_COLS * DIM_];     // Wqkv^T  [3072,1024]
__device__ float g_wt2[(size_t)DIM_ * DIM_];         // Wproj^T [1024,1024]
// Pre-packed KV (bf16x2 words, fragment-permuted):
// K: per (b,h): 2048 tokens x 32 words (dim pairs).  V: per (b,h): 64 dims x 1024 words (key pairs).
__device__ uint32_t g_kh[(size_t)BH_ * 2048 * 32];
__device__ uint32_t g_kl[(size_t)BH_ * 2048 * 32];
__device__ uint32_t g_vh[(size_t)BH_ * 64 * 1024];
__device__ uint32_t g_vl[(size_t)BH_ * 64 * 1024];

// ===========================================================================
// mma.sync helpers (baseline PTX ISA, works on target sm_100)
// ===========================================================================
__device__ __forceinline__ void mma_bf16(float* d,
                                         const uint32_t* a, uint32_t b0, uint32_t b1)
{
    asm volatile(
        "mma.sync.aligned.m16n8k16.row.col.f32.bf16.bf16.f32 "
        "{%0,%1,%2,%3}, {%4,%5,%6,%7}, {%8,%9}, {%0,%1,%2,%3};"
        : "+f"(d[0]), "+f"(d[1]), "+f"(d[2]), "+f"(d[3])
        : "r"(a[0]), "r"(a[1]), "r"(a[2]), "r"(a[3]), "r"(b0), "r"(b1));
}
__device__ __forceinline__ uint32_t pack_bf16(float lo, float hi) {
    uint32_t r;
    asm("cvt.rn.bf16x2.f32 %0, %1, %2;" : "=r"(r) : "f"(hi), "f"(lo));
    return r;
}
__device__ __forceinline__ float bf16lo_f(uint32_t p) { return __uint_as_float(p << 16); }
__device__ __forceinline__ float bf16hi_f(uint32_t p) { return __uint_as_float(p & 0xFFFF0000u); }
__device__ __forceinline__ void split_pair(float v0, float v1, uint32_t& hp, uint32_t& lp) {
    hp = pack_bf16(v0, v1);
    lp = pack_bf16(v0 - bf16lo_f(hp), v1 - bf16hi_f(hp));
}
// fragment permutation: word j of an 8-word k16 group -> stored position
__device__ __forceinline__ int perm8(int j) { return ((j & 3) << 1) | (j >> 2); }

// cp.async helpers
__device__ __forceinline__ void cp_async16(uint32_t saddr, const void* gptr) {
    asm volatile("cp.async.cg.shared.global [%0], [%1], 16;"
                 :: "r"(saddr), "l"(gptr) : "memory");
}
__device__ __forceinline__ void cp_commit() {
    asm volatile("cp.async.commit_group;" ::: "memory");
}
__device__ __forceinline__ void cp_wait1() {
    asm volatile("cp.async.wait_group 1;" ::: "memory");
}
__device__ __forceinline__ void cp_wait0() {
    asm volatile("cp.async.wait_group 0;" ::: "memory");
}

// ===========================================================================
// bf16x3 GEMM via m16n8k16 (validated R6): C[M,N] = A[M,K] @ Bt[N,K]^T
// ===========================================================================
#define GW 36
#define TILE_WORDS (128 * GW)
#define GEMM_SMEM_BYTES (4 * TILE_WORDS * 4)

__global__ __launch_bounds__(256) void gemm_bf16_kernel(
    int M, int N, int K,
    const float* __restrict__ A, const float* __restrict__ Bt,
    float* __restrict__ C)
{
    extern __shared__ uint32_t smw[];
    uint32_t* AH = smw;
    uint32_t* AL = smw + TILE_WORDS;
    uint32_t* BH = smw + 2 * TILE_WORDS;
    uint32_t* BL = smw + 3 * TILE_WORDS;

    const int tid = threadIdx.x;
    const int wid = tid >> 5;
    const int lid = tid & 31;
    const int gid = lid >> 2;
    const int tig = lid & 3;
    const int wm  = (wid & 3) * 32;
    const int wn  = (wid >> 2) * 64;

    const float* Ablk = A  + (size_t)blockIdx.y * 128 * K;
    const float* Bblk = Bt + (size_t)blockIdx.x * 128 * K;

    float4 ra[8], rb[8];

    auto LOADCH = [&](int c) {
        const int k0 = c * 64;
        #pragma unroll
        for (int i = 0; i < 8; i++) {
            int f = i * 256 + tid;
            int row = f >> 4, c4 = (f & 15) * 4;
            ra[i] = *reinterpret_cast<const float4*>(Ablk + (size_t)row * K + k0 + c4);
            rb[i] = *reinterpret_cast<const float4*>(Bblk + (size_t)row * K + k0 + c4);
        }
    };
    auto STORECH = [&]() {
        #pragma unroll
        for (int i = 0; i < 8; i++) {
            int f = i * 256 + tid;
            int row = f >> 4, c4 = (f & 15) * 4;
            int base = row * GW + (c4 >> 1);
            uint32_t hp, lp;
            split_pair(ra[i].x, ra[i].y, hp, lp);
            AH[base] = hp; AL[base] = lp;
            split_pair(ra[i].z, ra[i].w, hp, lp);
            AH[base + 1] = hp; AL[base + 1] = lp;
            split_pair(rb[i].x, rb[i].y, hp, lp);
            BH[base] = hp; BL[base] = lp;
            split_pair(rb[i].z, rb[i].w, hp, lp);
            BH[base + 1] = hp; BL[base + 1] = lp;
        }
    };

    float acc[2][8][4] = {};

    const int nch = K / 64;
    LOADCH(0);
    for (int c = 0; c < nch; c++) {
        STORECH();
        __syncthreads();
        if (c + 1 < nch) LOADCH(c + 1);

        #pragma unroll
        for (int ks = 0; ks < 4; ks++) {
            uint32_t afh[2][4], afl[2][4];
            #pragma unroll
            for (int mt = 0; mt < 2; mt++) {
                int r0 = wm + mt * 16 + gid;
                int p  = ks * 8;
                afh[mt][0] = AH[r0 * GW + p + tig];
                afh[mt][1] = AH[(r0 + 8) * GW + p + tig];
                afh[mt][2] = AH[r0 * GW + p + 4 + tig];
                afh[mt][3] = AH[(r0 + 8) * GW + p + 4 + tig];
                afl[mt][0] = AL[r0 * GW + p + tig];
                afl[mt][1] = AL[(r0 + 8) * GW + p + tig];
                afl[mt][2] = AL[r0 * GW + p + 4 + tig];
                afl[mt][3] = AL[(r0 + 8) * GW + p + 4 + tig];
            }
            #pragma unroll
            for (int nt = 0; nt < 8; nt++) {
                int n = wn + nt * 8 + gid;
                int p = ks * 8;
                uint32_t bh0 = BH[n * GW + p + tig];
                uint32_t bh1 = BH[n * GW + p + 4 + tig];
                uint32_t bl0 = BL[n * GW + p + tig];
                uint32_t bl1 = BL[n * GW + p + 4 + tig];
                #pragma unroll
                for (int mt = 0; mt < 2; mt++) {
                    float* d = acc[mt][nt];
                    mma_bf16(d, afh[mt], bh0, bh1);
                    mma_bf16(d, afh[mt], bl0, bl1);
                    mma_bf16(d, afl[mt], bh0, bh1);
                }
            }
        }
        __syncthreads();
    }

    float* Cblk = C + (size_t)blockIdx.y * 128 * N + blockIdx.x * 128;
    #pragma unroll
    for (int mt = 0; mt < 2; mt++) {
        #pragma unroll
        for (int nt = 0; nt < 8; nt++) {
            int r = wm + mt * 16 + gid;
            int cn = wn + nt * 8 + tig * 2;
            *reinterpret_cast<float2*>(Cblk + (size_t)r * N + cn) =
                make_float2(acc[mt][nt][0], acc[mt][nt][1]);
            *reinterpret_cast<float2*>(Cblk + (size_t)(r + 8) * N + cn) =
                make_float2(acc[mt][nt][2], acc[mt][nt][3]);
        }
    }
}

// ---------------------------------------------------------------------------
// Transpose: dst[N,K] = src[K,N]^T.
// ---------------------------------------------------------------------------
__global__ __launch_bounds__(256) void transpose_kernel(
    const float* __restrict__ src, float* __restrict__ dst, int K, int N)
{
    __shared__ float tile[32][33];
    int n0 = blockIdx.x * 32, k0 = blockIdx.y * 32;
    int tx = threadIdx.x, ty = threadIdx.y;
    #pragma unroll
    for (int i = 0; i < 4; i++)
        tile[ty + i * 8][tx] = src[(size_t)(k0 + ty + i * 8) * N + n0 + tx];
    __syncthreads();
    #pragma unroll
    for (int i = 0; i < 4; i++)
        dst[(size_t)(n0 + ty + i * 8) * K + k0 + tx] = tile[tx][ty + i * 8];
}

// ===========================================================================
// KV pre-pack: RoPE K, transpose V, split to bf16 hi/lo, permuted word order.
// Block = 64 tokens x one (b,h).  Vs row stride 68 floats -> float4-aligned.
// ===========================================================================
__global__ __launch_bounds__(256) void pack_kv_kernel(
    const float* __restrict__ qkv,
    const float* __restrict__ cosT,
    const float* __restrict__ sinT)
{
    __shared__ float Vs[64][68];
    const int bh = blockIdx.y;
    const int b  = bh >> 4;
    const int h  = bh & 15;
    const int t0 = blockIdx.x * 64;
    const int tid = threadIdx.x;

    uint32_t* KH = g_kh + (size_t)bh * 2048 * 32 + (size_t)t0 * 32;
    uint32_t* KL = g_kl + (size_t)bh * 2048 * 32 + (size_t)t0 * 32;

    #pragma unroll
    for (int i = 0; i < 4; i++) {
        int f = i * 256 + tid;          // 0..1023
        int r = f >> 4;                 // token 0..63
        int dp = (f & 15) * 4;          // dim 0..60
        int kt = t0 + r;
        const float* base = qkv + (size_t)(b * T_ + kt) * QKV_COLS + h * HD_ + dp;
        // K with RoPE
        float4 kv = *reinterpret_cast<const float4*>(base + DIM_);
        float c0 = cosT[kt * (HD_ / 2) + dp / 2];
        float s0 = sinT[kt * (HD_ / 2) + dp / 2];
        float c1 = cosT[kt * (HD_ / 2) + dp / 2 + 1];
        float s1 = sinT[kt * (HD_ / 2) + dp / 2 + 1];
        float k0r = kv.x * c0 - kv.y * s0;
        float k1r = kv.x * s0 + kv.y * c0;
        float k2r = kv.z * c1 - kv.w * s1;
        float k3r = kv.z * s1 + kv.w * c1;
        uint32_t hp, lp;
        int w0 = dp >> 1;               // word 0..31 (even)
        int g  = w0 >> 3, j = w0 & 7;
        split_pair(k0r, k1r, hp, lp);
        KH[r * 32 + g * 8 + perm8(j)] = hp;
        KL[r * 32 + g * 8 + perm8(j)] = lp;
        split_pair(k2r, k3r, hp, lp);
        KH[r * 32 + g * 8 + perm8(j + 1)] = hp;
        KL[r * 32 + g * 8 + perm8(j + 1)] = lp;
        // V tile into smem (row stride 68 -> 16B aligned rows)
        *reinterpret_cast<float4*>(&Vs[r][dp]) =
            *reinterpret_cast<const float4*>(base + 2 * DIM_);
    }
    __syncthreads();

    // V transposed: thread -> dim d, 8 key-pair words
    uint32_t* VH = g_vh + (size_t)bh * 64 * 1024 + (t0 >> 1);
    uint32_t* VL = g_vl + (size_t)bh * 64 * 1024 + (t0 >> 1);
    const int d  = tid >> 2;
    const int wb = (tid & 3) * 8;
    #pragma unroll
    for (int j = 0; j < 8; j++) {
        int w = wb + j;                 // tile word 0..31
        int g = w >> 3, jj = w & 7;
        uint32_t hp, lp;
        split_pair(Vs[2 * w][d], Vs[2 * w + 1][d], hp, lp);
        VH[(size_t)d * 1024 + g * 8 + perm8(jj)] = hp;
        VL[(size_t)d * 1024 + g * 8 + perm8(jj)] = lp;
    }
}

// ===========================================================================
// Tensor-core flash attention v2: pre-packed KV, cp.async double buffer.
// Block = 128 queries x one (b,h); 8 warps.
// smem: 2 buffers x [Kh|Kl|Vh|Vl], each 64 rows x 36 words.
// ===========================================================================
#define RSTR 36
#define ARR_WORDS (64 * RSTR)                  // 2304
#define BUF_WORDS (4 * ARR_WORDS)              // 9216
#define ATT_SMEM_BYTES (2 * BUF_WORDS * 4)     // 73728

__global__ __launch_bounds__(256) void attn_mma2_kernel(
    const float* __restrict__ qkv,
    const float* __restrict__ cosT,
    const float* __restrict__ sinT,
    float* __restrict__ out)
{
    extern __shared__ uint32_t sw[];

    const int bh = blockIdx.y;
    const int b  = bh >> 4;
    const int h  = bh & 15;
    const int tid = threadIdx.x;
    const int wid = tid >> 5;
    const int lid = tid & 31;
    const int gid = lid >> 2;
    const int tig = lid & 3;

    const int r0 = blockIdx.x * 128 + wid * 16 + gid;
    const int r1 = r0 + 8;
    const float scale = 0.125f;

    const uint32_t* GKH = g_kh + (size_t)bh * 2048 * 32;
    const uint32_t* GKL = g_kl + (size_t)bh * 2048 * 32;
    const uint32_t* GVH = g_vh + (size_t)bh * 64 * 1024;
    const uint32_t* GVL = g_vl + (size_t)bh * 64 * 1024;

    // --- Q fragments (RoPE + scale + bf16 hi/lo split) ---
    uint32_t QH[4][4], QL[4][4];
    #pragma unroll
    for (int ks = 0; ks < 4; ks++) {
        #pragma unroll
        for (int j = 0; j < 4; j++) {
            int row  = (j & 1) ? r1 : r0;
            int dim0 = ks * 16 + (j >> 1) * 8 + 2 * tig;
            const float* qp = qkv + (size_t)(b * T_ + row) * QKV_COLS + h * HD_ + dim0;
            float2 q = *reinterpret_cast<const float2*>(qp);
            float c = cosT[row * (HD_ / 2) + dim0 / 2];
            float s = sinT[row * (HD_ / 2) + dim0 / 2];
            float v0 = (q.x * c - q.y * s) * scale;
            float v1 = (q.x * s + q.y * c) * scale;
            split_pair(v0, v1, QH[ks][j], QL[ks][j]);
        }
    }

    // stage tile ti into buffer (ti&1) via cp.async (8 x 16B per thread)
    auto stage = [&](int ti) {
        uint32_t bufb = (uint32_t)(ti & 1) * BUF_WORDS;
        // K arrays: tile = 2048 contiguous words
        #pragma unroll
        for (int i = 0; i < 2; i++) {
            int q = i * 256 + tid;          // 0..511 (16B chunks)
            int row = q >> 3, ch = q & 7;
            uint32_t soff = bufb + row * RSTR + ch * 4;
            cp_async16((uint32_t)__cvta_generic_to_shared(sw + soff),
                       GKH + (size_t)ti * 2048 + q * 4);
            cp_async16((uint32_t)__cvta_generic_to_shared(sw + soff + ARR_WORDS),
                       GKL + (size_t)ti * 2048 + q * 4);
        }
        // V arrays: rows stride 1024, tile offset ti*32
        #pragma unroll
        for (int i = 0; i < 2; i++) {
            int q = i * 256 + tid;
            int row = q >> 3, ch = q & 7;
            uint32_t soff = bufb + 2 * ARR_WORDS + row * RSTR + ch * 4;
            cp_async16((uint32_t)__cvta_generic_to_shared(sw + soff),
                       GVH + (size_t)row * 1024 + ti * 32 + ch * 4);
            cp_async16((uint32_t)__cvta_generic_to_shared(sw + soff + ARR_WORDS),
                       GVL + (size_t)row * 1024 + ti * 32 + ch * 4);
        }
        cp_commit();
    };

    float O[8][4] = {};
    float m0 = -1e30f, m1 = -1e30f, l0 = 0.f, l1 = 0.f;

    stage(0);
    for (int t = 0; t < 32; t++) {
        if (t + 1 < 32) { stage(t + 1); cp_wait1(); }
        else            { cp_wait0(); }
        __syncthreads();

        const uint32_t* KhS = sw + (t & 1) * BUF_WORDS;
        const uint32_t* KlS = KhS + ARR_WORDS;
        const uint32_t* VhS = KhS + 2 * ARR_WORDS;
        const uint32_t* VlS = KhS + 3 * ARR_WORDS;

        // ---- S = Q K^T (bf16x3) ----
        float S[8][4] = {};
        #pragma unroll
        for (int ks = 0; ks < 4; ks++) {
            #pragma unroll
            for (int nt = 0; nt < 8; nt++) {
                int key = nt * 8 + gid;
                uint2 bhp = *reinterpret_cast<const uint2*>(&KhS[key * RSTR + ks * 8 + 2 * tig]);
                uint2 blp = *reinterpret_cast<const uint2*>(&KlS[key * RSTR + ks * 8 + 2 * tig]);
                mma_bf16(S[nt], QH[ks], bhp.x, bhp.y);
                mma_bf16(S[nt], QH[ks], blp.x, blp.y);
                mma_bf16(S[nt], QL[ks], bhp.x, bhp.y);
            }
        }

        // ---- online softmax ----
        float mt0 = m0, mt1 = m1;
        #pragma unroll
        for (int nt = 0; nt < 8; nt++) {
            mt0 = fmaxf(mt0, fmaxf(S[nt][0], S[nt][1]));
            mt1 = fmaxf(mt1, fmaxf(S[nt][2], S[nt][3]));
        }
        mt0 = fmaxf(mt0, __shfl_xor_sync(0xFFFFFFFFu, mt0, 1));
        mt0 = fmaxf(mt0, __shfl_xor_sync(0xFFFFFFFFu, mt0, 2));
        mt1 = fmaxf(mt1, __shfl_xor_sync(0xFFFFFFFFu, mt1, 1));
        mt1 = fmaxf(mt1, __shfl_xor_sync(0xFFFFFFFFu, mt1, 2));
        float cr0 = __expf(m0 - mt0), cr1 = __expf(m1 - mt1);
        m0 = mt0; m1 = mt1;
        float rs0 = 0.f, rs1 = 0.f;
        #pragma unroll
        for (int nt = 0; nt < 8; nt++) {
            S[nt][0] = __expf(S[nt][0] - m0);
            S[nt][1] = __expf(S[nt][1] - m0);
            S[nt][2] = __expf(S[nt][2] - m1);
            S[nt][3] = __expf(S[nt][3] - m1);
            rs0 += S[nt][0] + S[nt][1];
            rs1 += S[nt][2] + S[nt][3];
        }
        rs0 += __shfl_xor_sync(0xFFFFFFFFu, rs0, 1);
        rs0 += __shfl_xor_sync(0xFFFFFFFFu, rs0, 2);
        rs1 += __shfl_xor_sync(0xFFFFFFFFu, rs1, 1);
        rs1 += __shfl_xor_sync(0xFFFFFFFFu, rs1, 2);
        l0 = l0 * cr0 + rs0;
        l1 = l1 * cr1 + rs1;
        #pragma unroll
        for (int nt = 0; nt < 8; nt++) {
            O[nt][0] *= cr0; O[nt][1] *= cr0;
            O[nt][2] *= cr1; O[nt][3] *= cr1;
        }

        // ---- O += P V (bf16x3) ----
        #pragma unroll
        for (int ks = 0; ks < 4; ks++) {
            uint32_t pH[4], pL[4];
            split_pair(S[2 * ks][0],     S[2 * ks][1],     pH[0], pL[0]);
            split_pair(S[2 * ks][2],     S[2 * ks][3],     pH[1], pL[1]);
            split_pair(S[2 * ks + 1][0], S[2 * ks + 1][1], pH[2], pL[2]);
            split_pair(S[2 * ks + 1][2], S[2 * ks + 1][3], pH[3], pL[3]);
            #pragma unroll
            for (int nt = 0; nt < 8; nt++) {
                int dim = nt * 8 + gid;
                uint2 bhp = *reinterpret_cast<const uint2*>(&VhS[dim * RSTR + ks * 8 + 2 * tig]);
                uint2 blp = *reinterpret_cast<const uint2*>(&VlS[dim * RSTR + ks * 8 + 2 * tig]);
                mma_bf16(O[nt], pH, bhp.x, bhp.y);
                mma_bf16(O[nt], pH, blp.x, blp.y);
                mma_bf16(O[nt], pL, bhp.x, bhp.y);
            }
        }
        __syncthreads();
    }

    // ---- finalize + write ----
    float i0 = 1.f / l0, i1 = 1.f / l1;
    float* o0 = out + (size_t)(b * T_ + r0) * DIM_ + h * HD_;
    float* o1 = out + (size_t)(b * T_ + r1) * DIM_ + h * HD_;
    #pragma unroll
    for (int nt = 0; nt < 8; nt++) {
        int cn = nt * 8 + 2 * tig;
        *reinterpret_cast<float2*>(o0 + cn) = make_float2(O[nt][0] * i0, O[nt][1] * i0);
        *reinterpret_cast<float2*>(o1 + cn) = make_float2(O[nt][2] * i1, O[nt][3] * i1);
    }
}

// ---------------------------------------------------------------------------
// kernel_launch
// ---------------------------------------------------------------------------
extern "C" void kernel_launch(void* const* d_in, const int* in_sizes, int n_in,
                              void* d_out, int out_size)
{
    (void)in_sizes; (void)n_in; (void)out_size;
    const float* x     = (const float*)d_in[0];
    const float* fcos  = (const float*)d_in[1];
    const float* fsin  = (const float*)d_in[2];
    // d_in[3] = mask, all-True, unused
    const float* Wqkv  = (const float*)d_in[4];
    const float* Wproj = (const float*)d_in[5];
    float* out = (float*)d_out;

    float* qkv;  cudaGetSymbolAddress((void**)&qkv,  g_qkv);
    float* attn; cudaGetSymbolAddress((void**)&attn, g_attn);
    float* wt1;  cudaGetSymbolAddress((void**)&wt1,  g_wt1);
    float* wt2;  cudaGetSymbolAddress((void**)&wt2,  g_wt2);

    cudaFuncSetAttribute(gemm_bf16_kernel,
                         cudaFuncAttributeMaxDynamicSharedMemorySize, GEMM_SMEM_BYTES);
    cudaFuncSetAttribute(attn_mma2_kernel,
                         cudaFuncAttributeMaxDynamicSharedMemorySize, ATT_SMEM_BYTES);

    // 0) transpose weights to K-major [N,K]
    {
        dim3 blk(32, 8);
        transpose_kernel<<<dim3(QKV_COLS / 32, DIM_ / 32), blk>>>(Wqkv, wt1, DIM_, QKV_COLS);
        transpose_kernel<<<dim3(DIM_ / 32, DIM_ / 32), blk>>>(Wproj, wt2, DIM_, DIM_);
    }
    // 1) qkv = x @ Wqkv   (mma.sync bf16x3)
    {
        dim3 grid(QKV_COLS / 128, NTOK / 128);
        gemm_bf16_kernel<<<grid, 256, GEMM_SMEM_BYTES>>>(NTOK, QKV_COLS, DIM_, x, wt1, qkv);
    }
    // 2) pack K (RoPE) + V to bf16 hi/lo fragment layout
    {
        dim3 grid(T_ / 64, BH_);
        pack_kv_kernel<<<grid, 256>>>(qkv, fcos, fsin);
    }
    // 3) attention (tensor-core, double-buffered) -> attn
    {
        dim3 grid(T_ / 128, BH_);
        attn_mma2_kernel<<<grid, 256, ATT_SMEM_BYTES>>>(qkv, fcos, fsin, attn);
    }
    // 4) out = attn @ Wproj  (mma.sync bf16x3)
    {
        dim3 grid(DIM_ / 128, NTOK / 128);
        gemm_bf16_kernel<<<grid, 256, GEMM_SMEM_BYTES>>>(NTOK, DIM_, DIM_, attn, wt2, out);
    }
}